// round 15
// baseline (speedup 1.0000x reference)
#include <cuda_runtime.h>
#include <cuda_fp16.h>
#include <math.h>

#define Nn 10000
#define Ne 160000
#define NSPLIT 5000

// ---------------- scratch (device globals; no allocation allowed) ----------
__device__ float4  g_v_up4[Nn*64];          // [n][c] = (vx,vy,vz, s_up)
__device__ float   g_skip_s[Nn*128];
__device__ float   g_skip_v[Nn*192];        // [n][c*3+i]
__device__ float   g_agg_s[Nn*128];
__device__ float   g_agg_v[Nn*576];         // [n][i3][c]
__device__ __half2 g_mixh [(size_t)Ne*128]; // [e][c][2] : (x0,x1),(x2,x3)
__device__ __half  g_mixwh[(size_t)Ne*64];  // [e][c] : x4
__device__ int     g_cw  [2*Nn];            // [0:Nn)=cnt, [Nn:2Nn)=wp
__device__ int     g_off [Nn+1];
__device__ int     g_list[Ne];              // CSR slot -> edge
__device__ int     g_snd [Ne];              // CSR slot -> sender
__device__ float4  g_uvec4[Ne];             // CSR slot -> unit vector

__device__ __forceinline__ float sw(float x){ return x/(1.f+__expf(-x)); }

// ---- packed f32x2 helpers (sm_100+) ----
typedef unsigned long long u64t;
__device__ __forceinline__ u64t pk(float lo, float hi){
    u64t r; asm("mov.b64 %0, {%1,%2};" : "=l"(r) : "f"(lo), "f"(hi)); return r;
}
__device__ __forceinline__ void fma2(u64t &d, u64t a, u64t b){
    asm("fma.rn.f32x2 %0, %1, %2, %0;" : "+l"(d) : "l"(a), "l"(b));
}
__device__ __forceinline__ float2 up2(u64t v){
    float2 r; asm("mov.b64 {%0,%1}, %2;" : "=f"(r.x), "=f"(r.y) : "l"(v)); return r;
}

// ---------------- K1: node prep (v_up4 incl s_up, skip_s, skip_v) -----------
__global__ __launch_bounds__(256) void k_node_prep(
    const float* __restrict__ ns, const float* __restrict__ nv,
    const int*   __restrict__ spec,
    const float* __restrict__ Wss, const float* __restrict__ Wsv,
    const float* __restrict__ Wus, const float* __restrict__ Wuv)
{
    __shared__ float sWus[4096], sWuv[4096];
    __shared__ float stage[8][256];
    int tid = threadIdx.x;
    for(int i=tid;i<4096;i+=256){ sWus[i]=Wus[i]; sWuv[i]=Wuv[i]; }
    __syncthreads();
    int warp = tid>>5, lane = tid&31;
    int gw = blockIdx.x*8+warp, nw = gridDim.x*8;
    for(int n=gw; n<Nn; n+=nw){
        float* st = stage[warp];
        for(int i=lane;i<64;i+=32)  st[i]    = ns[n*64+i];
        for(int i=lane;i<192;i+=32) st[64+i] = nv[n*192+i];
        __syncwarp();
        int sp = spec[n];
        const float* wss = Wss + sp*8192;   // [64][128]
        const float* wsv = Wsv + sp*4096;   // [64][64]
        float asu0=0.f, asu1=0.f;
        float avu[2][3]={{0,0,0},{0,0,0}};
        float aks[4]={0,0,0,0};
        float akv[2][3]={{0,0,0},{0,0,0}};
        for(int c=0;c<64;c++){
            float s  = st[c];
            float v0 = st[64+3*c], v1 = st[64+3*c+1], v2 = st[64+3*c+2];
            float w0 = sWus[c*64+lane], w1 = sWus[c*64+lane+32];
            asu0 += s*w0; asu1 += s*w1;
            float u0 = sWuv[c*64+lane], u1 = sWuv[c*64+lane+32];
            avu[0][0]+=v0*u0; avu[0][1]+=v1*u0; avu[0][2]+=v2*u0;
            avu[1][0]+=v0*u1; avu[1][1]+=v1*u1; avu[1][2]+=v2*u1;
            #pragma unroll
            for(int j=0;j<4;j++) aks[j] += s*wss[c*128+lane+32*j];
            float k0 = wsv[c*64+lane], k1 = wsv[c*64+lane+32];
            akv[0][0]+=v0*k0; akv[0][1]+=v1*k0; akv[0][2]+=v2*k0;
            akv[1][0]+=v0*k1; akv[1][1]+=v1*k1; akv[1][2]+=v2*k1;
        }
        const float sc = 0.125f;   // 1/sqrt(64)
        g_v_up4[n*64+lane]    = make_float4(avu[0][0]*sc, avu[0][1]*sc, avu[0][2]*sc, asu0*sc);
        g_v_up4[n*64+lane+32] = make_float4(avu[1][0]*sc, avu[1][1]*sc, avu[1][2]*sc, asu1*sc);
        #pragma unroll
        for(int j=0;j<4;j++) g_skip_s[n*128+lane+32*j] = aks[j]*sc;
        #pragma unroll
        for(int j=0;j<2;j++)
            #pragma unroll
            for(int i=0;i<3;i++)
                g_skip_v[n*192+3*(lane+32*j)+i] = akv[j][i]*sc;
        __syncwarp();
    }
}

// ---------------- CSR build: hist -> scan -> bucket --------------------------
__global__ __launch_bounds__(256) void k_hist(const int* __restrict__ recv){
    int e = blockIdx.x*256+threadIdx.x;
    if(e<Ne) atomicAdd(&g_cw[recv[e]],1);
}
__global__ __launch_bounds__(1024) void k_scan(){
    __shared__ int part[1024];
    int tid = threadIdx.x;
    int st = tid*10;
    int loc[10]; int s=0;
    #pragma unroll
    for(int i=0;i<10;i++){
        int v = (st+i<Nn)? g_cw[st+i] : 0;
        loc[i]=s; s+=v;
    }
    part[tid]=s; __syncthreads();
    for(int d=1; d<1024; d<<=1){
        int v = (tid>=d)? part[tid-d] : 0;
        __syncthreads();
        part[tid]+=v;
        __syncthreads();
    }
    int base = (tid==0)? 0 : part[tid-1];
    #pragma unroll
    for(int i=0;i<10;i++) if(st+i<Nn) g_off[st+i]=base+loc[i];
    if(tid==1023) g_off[Nn]=part[1023];
}
__global__ __launch_bounds__(256) void k_bucket(
    const int* __restrict__ recv, const int* __restrict__ send,
    const float* __restrict__ vecs)
{
    int e = blockIdx.x*256+threadIdx.x;
    if(e<Ne){
        int r = recv[e];
        int p = atomicAdd(&g_cw[Nn+r],1);
        int slot = g_off[r]+p;
        g_list[slot] = e;
        g_snd[slot]  = send[e];
        float vx=vecs[3*e], vy=vecs[3*e+1], vz=vecs[3*e+2];
        float invr = rsqrtf(vx*vx+vy*vy+vz*vz);
        g_uvec4[slot] = make_float4(vx*invr, vy*invr, vz*invr, 0.f);
    }
}

// ---------------- K2: radial MLP -> g_mixh/g_mixwh (f32x2, 64-edge tiles) ---
#define MLP_SMEM_FLOATS (512+4096+20480+512+4352+4352)
__global__ __launch_bounds__(256) void k_mlp(
    const float* __restrict__ vecs,
    const float* __restrict__ W1, const float* __restrict__ W2,
    const float* __restrict__ W3)
{
    extern __shared__ float sm[];
    float* sW1  = sm;
    float* sW2  = sm+512;
    float* sW3  = sm+4608;
    float* sRadT= sm+25088;      // [k][64]
    float* sH1T = sm+25600;      // [k][68]
    float* sH2T = sm+29952;      // [k][68]
    int tid = threadIdx.x;
    for(int i=tid;i<512;i+=256)   sW1[i]=W1[i];
    for(int i=tid;i<4096;i+=256)  sW2[i]=W2[i];
    for(int i=tid;i<20480;i+=256) sW3[i]=W3[i];
    __syncthreads();

    const float PI = 3.14159265358979f;
    const float SQRT2 = 1.41421356237f;

    int e1  = tid&63,  og1 = tid>>6;
    int ebl = (tid&15)*4, obl = (tid>>4)*4;
    int eg  = tid>>5,  ot  = tid&31;

    for(int tile=blockIdx.x; tile<Ne/64; tile+=gridDim.x){
        int ebase = tile*64;
        if(tid < 64){
            int e = ebase + tid;
            float x = vecs[3*e], y = vecs[3*e+1], z = vecs[3*e+2];
            float r = sqrtf(x*x+y*y+z*z);
            float r2 = r*r, r3 = r2*r;
            float x6 = r3*r3;
            float env = 1.f - 28.f*x6 + 48.f*x6*r - 21.f*x6*r2;
            if(r >= 1.f) env = 0.f;
            float coef = SQRT2*env/r;
            float pr = PI*r;
            #pragma unroll
            for(int k=0;k<8;k++) sRadT[k*64+tid] = coef*sinf((float)(k+1)*pr);
        }
        __syncthreads();
        {
            u64t a[8];
            #pragma unroll
            for(int j=0;j<8;j++) a[j]=0ULL;
            #pragma unroll
            for(int k=0;k<8;k++){
                float r = sRadT[k*64+e1];
                u64t rp = pk(r,r);
                #pragma unroll
                for(int j=0;j<8;j++){
                    u64t w = *(const u64t*)&sW1[k*64 + og1*16 + 2*j];
                    fma2(a[j], rp, w);
                }
            }
            #pragma unroll
            for(int j=0;j<8;j++){
                float2 v = up2(a[j]);
                sH1T[(og1*16+2*j)*68 + e1]   = sw(v.x*0.35355339059f);
                sH1T[(og1*16+2*j+1)*68 + e1] = sw(v.y*0.35355339059f);
            }
        }
        __syncthreads();
        {
            u64t b[4][2];
            #pragma unroll
            for(int i=0;i<4;i++){ b[i][0]=0ULL; b[i][1]=0ULL; }
            for(int k=0;k<64;k++){
                const float4 h = *(const float4*)&sH1T[k*68 + ebl];
                const ulonglong2 w = *(const ulonglong2*)&sW2[k*64 + obl];
                u64t h0=pk(h.x,h.x), h1=pk(h.y,h.y), h2v=pk(h.z,h.z), h3=pk(h.w,h.w);
                fma2(b[0][0],h0,w.x); fma2(b[0][1],h0,w.y);
                fma2(b[1][0],h1,w.x); fma2(b[1][1],h1,w.y);
                fma2(b[2][0],h2v,w.x); fma2(b[2][1],h2v,w.y);
                fma2(b[3][0],h3,w.x); fma2(b[3][1],h3,w.y);
            }
            #pragma unroll
            for(int i=0;i<4;i++){
                #pragma unroll
                for(int p=0;p<2;p++){
                    float2 v = up2(b[i][p]);
                    sH2T[(obl+2*p)*68 + ebl+i]   = sw(v.x*0.125f);
                    sH2T[(obl+2*p+1)*68 + ebl+i] = sw(v.y*0.125f);
                }
            }
        }
        __syncthreads();
        {
            u64t m[8][5];
            #pragma unroll
            for(int i=0;i<8;i++)
                #pragma unroll
                for(int j=0;j<5;j++) m[i][j]=0ULL;
            for(int k=0;k<64;k++){
                const float4 ha = *(const float4*)&sH2T[k*68 + eg*8];
                const float4 hb = *(const float4*)&sH2T[k*68 + eg*8 + 4];
                u64t wj[5];
                #pragma unroll
                for(int j=0;j<5;j++)
                    wj[j] = *(const u64t*)&sW3[k*320 + 2*ot + 64*j];
                u64t hp;
                hp=pk(ha.x,ha.x);
                #pragma unroll
                for(int j=0;j<5;j++) fma2(m[0][j],hp,wj[j]);
                hp=pk(ha.y,ha.y);
                #pragma unroll
                for(int j=0;j<5;j++) fma2(m[1][j],hp,wj[j]);
                hp=pk(ha.z,ha.z);
                #pragma unroll
                for(int j=0;j<5;j++) fma2(m[2][j],hp,wj[j]);
                hp=pk(ha.w,ha.w);
                #pragma unroll
                for(int j=0;j<5;j++) fma2(m[3][j],hp,wj[j]);
                hp=pk(hb.x,hb.x);
                #pragma unroll
                for(int j=0;j<5;j++) fma2(m[4][j],hp,wj[j]);
                hp=pk(hb.y,hb.y);
                #pragma unroll
                for(int j=0;j<5;j++) fma2(m[5][j],hp,wj[j]);
                hp=pk(hb.z,hb.z);
                #pragma unroll
                for(int j=0;j<5;j++) fma2(m[6][j],hp,wj[j]);
                hp=pk(hb.w,hb.w);
                #pragma unroll
                for(int j=0;j<5;j++) fma2(m[7][j],hp,wj[j]);
            }
            const float S = 0.03125f;  // (1/8)*(1/4)
            #pragma unroll
            for(int i=0;i<8;i++){
                int e = ebase + eg*8 + i;
                float2 v0=up2(m[i][0]), v1=up2(m[i][1]), v2=up2(m[i][2]);
                float2 v3=up2(m[i][3]), v4=up2(m[i][4]);
                __half2 a01 = __floats2half2_rn(v0.x*S, v1.x*S);
                __half2 a23 = __floats2half2_rn(v2.x*S, v3.x*S);
                __half2 b01 = __floats2half2_rn(v0.y*S, v1.y*S);
                __half2 b23 = __floats2half2_rn(v2.y*S, v3.y*S);
                uint4 stv;
                stv.x = *(unsigned int*)&a01;
                stv.y = *(unsigned int*)&a23;
                stv.z = *(unsigned int*)&b01;
                stv.w = *(unsigned int*)&b23;
                *reinterpret_cast<uint4*>(&g_mixh[(size_t)e*128 + 4*ot]) = stv;
                __half2 wv = __floats2half2_rn(v4.x*S, v4.y*S);
                *reinterpret_cast<__half2*>(&g_mixwh[(size_t)e*64 + 2*ot]) = wv;
            }
        }
        __syncthreads();
    }
}

// ---------------- K3: CSR gather-aggregate (fp16 mix stream, node range) ----
__global__ __launch_bounds__(256) void k_agg(int n0, int n1)
{
    __shared__ int slist[8][64];
    __shared__ int ssnd [8][64];
    int warp = threadIdx.x>>5, lane = threadIdx.x&31;
    const float SQRT3 = 1.73205080757f;
    const float CRS   = 1.22474487139f;  // sqrt(3)/sqrt(2)
    int n = n0 + blockIdx.x*8 + warp;
    if(n >= n1) return;
    int k0 = g_off[n], k1 = g_off[n+1];
    float as[2]={0,0}, ats[2]={0,0};
    float amv[2][3]={{0,0,0},{0,0,0}};
    float asc[2][3]={{0,0,0},{0,0,0}};
    float acr[2][3]={{0,0,0},{0,0,0}};
    int* lst = slist[warp];
    int* snd = ssnd[warp];
    for(int base=k0; base<k1; base+=64){
        int chunk = min(64, k1-base);
        for(int i=lane;i<chunk;i+=32){
            lst[i] = g_list[base+i];
            snd[i] = g_snd[base+i];
        }
        __syncwarp();
        #pragma unroll 4
        for(int i=0;i<chunk;i++){
            int slot = base+i;
            int e = lst[i];
            int s = snd[i];
            float4 u4 = g_uvec4[slot];
            float ux=u4.x, uy=u4.y, uz=u4.z;
            const float4*  vu = g_v_up4 + (size_t)s*64;
            const __half2* mh = g_mixh + (size_t)e*128;
            const __half*  mw = g_mixwh + (size_t)e*64;
            #pragma unroll
            for(int t=0;t<2;t++){
                int c = lane + 32*t;
                float4 vv = vu[c];            // (vx,vy,vz, s_up)
                uint2 raw = __ldcs(reinterpret_cast<const uint2*>(mh + (size_t)c*2));
                __half2 h01 = *(__half2*)&raw.x;
                __half2 h23 = *(__half2*)&raw.y;
                float2 f01 = __half22float2(h01);
                float2 f23 = __half22float2(h23);
                float x0=f01.x, x1=f01.y, x2=f23.x, x3=f23.y;
                float x4 = __half2float(mw[c]);
                float  ms = vv.w;
                as[t]  += ms*x0;
                ats[t] += (vv.x*ux+vv.y*uy+vv.z*uz)*x1;
                amv[t][0] += vv.x*x2; amv[t][1] += vv.y*x2; amv[t][2] += vv.z*x2;
                float s3 = ms*SQRT3*x3;
                asc[t][0] += s3*ux; asc[t][1] += s3*uy; asc[t][2] += s3*uz;
                float c4 = CRS*x4;
                acr[t][0] += (vv.y*uz-vv.z*uy)*c4;
                acr[t][1] += (vv.z*ux-vv.x*uz)*c4;
                acr[t][2] += (vv.x*uy-vv.y*ux)*c4;
            }
        }
        __syncwarp();
    }
    #pragma unroll
    for(int t=0;t<2;t++){
        int c = lane + 32*t;
        g_agg_s[n*128+c]     = as[t];
        g_agg_s[n*128+64+c]  = ats[t];
        #pragma unroll
        for(int i3=0;i3<3;i3++){
            g_agg_v[(size_t)n*576 + i3*192 + c]       = amv[t][i3];
            g_agg_v[(size_t)n*576 + i3*192 + 64 + c]  = asc[t][i3];
            g_agg_v[(size_t)n*576 + i3*192 + 128 + c] = acr[t][i3];
        }
    }
}

// ---------------- K4: down-projection + skip + gate (node range) ------------
// smem floats: Wds 16384 | Wdv 12288 | stage 8*704
#define OUT_SMEM_FLOATS (16384+12288+5632)
__global__ __launch_bounds__(256) void k_node_out(
    const float* __restrict__ Wds, const float* __restrict__ Wdv,
    float* __restrict__ out, int n0, int n1)
{
    extern __shared__ float sm[];
    float* sWds = sm;
    float* sWdv = sm+16384;
    float* sAgg = sm+16384+12288;
    int tid = threadIdx.x;
    for(int i=tid;i<16384;i+=256) sWds[i]=Wds[i];
    for(int i=tid;i<12288;i+=256) sWdv[i]=Wdv[i];
    __syncthreads();
    int warp = tid>>5, lane = tid&31;
    int gw = blockIdx.x*8+warp, nw = gridDim.x*8;
    const float ISNS = 0.08838834765f;  // 1/sqrt(128)
    const float ISNV = 0.07216878365f;  // 1/sqrt(192)
    float* st = sAgg + warp*704;
    for(int n=n0+gw; n<n1; n+=nw){
        for(int i=lane;i<128;i+=32) st[i]     = g_agg_s[n*128+i];
        for(int i=lane;i<576;i+=32) st[128+i] = g_agg_v[(size_t)n*576+i];
        __syncwarp();
        float os[4]={0,0,0,0};
        for(int c=0;c<128;c++){
            float a = st[c];
            #pragma unroll
            for(int j=0;j<4;j++) os[j] += a*sWds[c*128+lane+32*j];
        }
        float ov[2][3]={{0,0,0},{0,0,0}};
        for(int c=0;c<192;c++){
            float a0 = st[128+c], a1 = st[128+192+c], a2 = st[128+384+c];
            #pragma unroll
            for(int j=0;j<2;j++){
                float w = sWdv[c*64+lane+32*j];
                ov[j][0]+=a0*w; ov[j][1]+=a1*w; ov[j][2]+=a2*w;
            }
        }
        #pragma unroll
        for(int j=0;j<4;j++) os[j] = os[j]*ISNS + g_skip_s[n*128+lane+32*j];
        #pragma unroll
        for(int j=0;j<2;j++)
            #pragma unroll
            for(int i=0;i<3;i++)
                ov[j][i] = ov[j][i]*ISNV + g_skip_v[(size_t)n*192+3*(lane+32*j)+i];
        float g0 = sw(os[2]), g1 = sw(os[3]);
        float* o = out + (size_t)n*256;
        o[lane]    = sw(os[0]);
        o[lane+32] = sw(os[1]);
        #pragma unroll
        for(int i=0;i<3;i++){
            o[64+3*lane+i]      = ov[0][i]*g0;
            o[64+3*(lane+32)+i] = ov[1][i]*g1;
        }
        __syncwarp();
    }
}

// ---------------- launch ----------------------------------------------------
extern "C" void kernel_launch(void* const* d_in, const int* in_sizes, int n_in,
                              void* d_out, int out_size)
{
    const float* vectors  = (const float*)d_in[0];
    const float* node_s   = (const float*)d_in[1];
    const float* node_v   = (const float*)d_in[2];
    const int*   spec     = (const int*)  d_in[3];
    const int*   senders  = (const int*)  d_in[4];
    const int*   receivers= (const int*)  d_in[5];
    const float* Wss      = (const float*)d_in[6];
    const float* Wsv      = (const float*)d_in[7];
    const float* Wus      = (const float*)d_in[8];
    const float* Wuv      = (const float*)d_in[9];
    const float* W1       = (const float*)d_in[10];
    const float* W2       = (const float*)d_in[11];
    const float* W3       = (const float*)d_in[12];
    const float* Wds      = (const float*)d_in[13];
    const float* Wdv      = (const float*)d_in[14];
    float* out = (float*)d_out;

    void *pcw;
    cudaGetSymbolAddress(&pcw, g_cw);

    cudaFuncSetAttribute(k_mlp, cudaFuncAttributeMaxDynamicSharedMemorySize,
                         MLP_SMEM_FLOATS*4);
    cudaFuncSetAttribute(k_node_out, cudaFuncAttributeMaxDynamicSharedMemorySize,
                         OUT_SMEM_FLOATS*4);

    cudaStream_t s2;
    cudaStreamCreateWithFlags(&s2, cudaStreamNonBlocking);
    cudaEvent_t evF, evJ, evA1, evO1;
    cudaEventCreateWithFlags(&evF,  cudaEventDisableTiming);
    cudaEventCreateWithFlags(&evJ,  cudaEventDisableTiming);
    cudaEventCreateWithFlags(&evA1, cudaEventDisableTiming);
    cudaEventCreateWithFlags(&evO1, cudaEventDisableTiming);

    cudaEventRecord(evF, 0);
    cudaStreamWaitEvent(s2, evF, 0);

    // side stream: CSR + node prep
    cudaMemsetAsync(pcw, 0, 2*Nn*sizeof(int), s2);
    k_hist  <<<(Ne+255)/256, 256, 0, s2>>>(receivers);
    k_scan  <<<1, 1024, 0, s2>>>();
    k_bucket<<<(Ne+255)/256, 256, 0, s2>>>(receivers, senders, vectors);
    k_node_prep<<<1250, 256, 0, s2>>>(node_s, node_v, spec, Wss, Wsv, Wus, Wuv);
    cudaEventRecord(evJ, s2);

    // main: mlp, then agg half 1
    k_mlp<<<148, 256, MLP_SMEM_FLOATS*4>>>(vectors, W1, W2, W3);
    cudaStreamWaitEvent(0, evJ, 0);
    k_agg<<<(NSPLIT+7)/8, 256>>>(0, NSPLIT);
    cudaEventRecord(evA1, 0);

    // main: agg half 2  ||  side: out half 1
    k_agg<<<(Nn-NSPLIT+7)/8, 256>>>(NSPLIT, Nn);
    cudaStreamWaitEvent(s2, evA1, 0);
    k_node_out<<<148, 256, OUT_SMEM_FLOATS*4, s2>>>(Wds, Wdv, out, 0, NSPLIT);
    cudaEventRecord(evO1, s2);

    // main: out half 2 (after its agg, and join side before finishing)
    cudaStreamWaitEvent(0, evO1, 0);
    k_node_out<<<148, 256, OUT_SMEM_FLOATS*4>>>(Wds, Wdv, out, NSPLIT, Nn);

    cudaEventDestroy(evF);
    cudaEventDestroy(evJ);
    cudaEventDestroy(evA1);
    cudaEventDestroy(evO1);
    cudaStreamDestroy(s2);
}

// round 17
// speedup vs baseline: 1.0605x; 1.0605x over previous
#include <cuda_runtime.h>
#include <cuda_fp16.h>
#include <math.h>

#define Nn 10000
#define Ne 160000

// ---------------- scratch (device globals; no allocation allowed) ----------
__device__ float4  g_v_up4[Nn*64];          // [n][c] = (vx,vy,vz, s_up)
__device__ float   g_skip_s[Nn*128];
__device__ float   g_skip_v[Nn*192];        // [n][c*3+i]
__device__ float   g_agg_s[Nn*128];
__device__ float   g_agg_v[Nn*576];         // [n][i3][c]
__device__ __half2 g_mixh [(size_t)Ne*128]; // [e][c][2] : (x0,x1),(x2,x3)
__device__ __half  g_mixwh[(size_t)Ne*64];  // [e][c] : x4
__device__ int     g_cw  [2*Nn];            // [0:Nn)=cnt, [Nn:2Nn)=wp
__device__ int     g_off [Nn+1];
__device__ int     g_list[Ne];              // CSR slot -> edge
__device__ int     g_snd [Ne];              // CSR slot -> sender
__device__ float4  g_uvec4[Ne];             // CSR slot -> unit vector

__device__ __forceinline__ float sw(float x){ return x/(1.f+__expf(-x)); }

// ---- packed f32x2 helpers (sm_100+) ----
typedef unsigned long long u64t;
__device__ __forceinline__ u64t pk(float lo, float hi){
    u64t r; asm("mov.b64 %0, {%1,%2};" : "=l"(r) : "f"(lo), "f"(hi)); return r;
}
__device__ __forceinline__ void fma2(u64t &d, u64t a, u64t b){
    asm("fma.rn.f32x2 %0, %1, %2, %0;" : "+l"(d) : "l"(a), "l"(b));
}
__device__ __forceinline__ float2 up2(u64t v){
    float2 r; asm("mov.b64 {%0,%1}, %2;" : "=f"(r.x), "=f"(r.y) : "l"(v)); return r;
}

// ---------------- K1: node prep (v_up4 incl s_up, skip_s, skip_v) -----------
__global__ __launch_bounds__(256) void k_node_prep(
    const float* __restrict__ ns, const float* __restrict__ nv,
    const int*   __restrict__ spec,
    const float* __restrict__ Wss, const float* __restrict__ Wsv,
    const float* __restrict__ Wus, const float* __restrict__ Wuv)
{
    __shared__ float sWus[4096], sWuv[4096];
    __shared__ float stage[8][256];
    int tid = threadIdx.x;
    for(int i=tid;i<4096;i+=256){ sWus[i]=Wus[i]; sWuv[i]=Wuv[i]; }
    __syncthreads();
    int warp = tid>>5, lane = tid&31;
    int gw = blockIdx.x*8+warp, nw = gridDim.x*8;
    for(int n=gw; n<Nn; n+=nw){
        float* st = stage[warp];
        for(int i=lane;i<64;i+=32)  st[i]    = ns[n*64+i];
        for(int i=lane;i<192;i+=32) st[64+i] = nv[n*192+i];
        __syncwarp();
        int sp = spec[n];
        const float* wss = Wss + sp*8192;   // [64][128]
        const float* wsv = Wsv + sp*4096;   // [64][64]
        float asu0=0.f, asu1=0.f;
        float avu[2][3]={{0,0,0},{0,0,0}};
        float aks[4]={0,0,0,0};
        float akv[2][3]={{0,0,0},{0,0,0}};
        for(int c=0;c<64;c++){
            float s  = st[c];
            float v0 = st[64+3*c], v1 = st[64+3*c+1], v2 = st[64+3*c+2];
            float w0 = sWus[c*64+lane], w1 = sWus[c*64+lane+32];
            asu0 += s*w0; asu1 += s*w1;
            float u0 = sWuv[c*64+lane], u1 = sWuv[c*64+lane+32];
            avu[0][0]+=v0*u0; avu[0][1]+=v1*u0; avu[0][2]+=v2*u0;
            avu[1][0]+=v0*u1; avu[1][1]+=v1*u1; avu[1][2]+=v2*u1;
            #pragma unroll
            for(int j=0;j<4;j++) aks[j] += s*wss[c*128+lane+32*j];
            float k0 = wsv[c*64+lane], k1 = wsv[c*64+lane+32];
            akv[0][0]+=v0*k0; akv[0][1]+=v1*k0; akv[0][2]+=v2*k0;
            akv[1][0]+=v0*k1; akv[1][1]+=v1*k1; akv[1][2]+=v2*k1;
        }
        const float sc = 0.125f;   // 1/sqrt(64)
        g_v_up4[n*64+lane]    = make_float4(avu[0][0]*sc, avu[0][1]*sc, avu[0][2]*sc, asu0*sc);
        g_v_up4[n*64+lane+32] = make_float4(avu[1][0]*sc, avu[1][1]*sc, avu[1][2]*sc, asu1*sc);
        #pragma unroll
        for(int j=0;j<4;j++) g_skip_s[n*128+lane+32*j] = aks[j]*sc;
        #pragma unroll
        for(int j=0;j<2;j++)
            #pragma unroll
            for(int i=0;i<3;i++)
                g_skip_v[n*192+3*(lane+32*j)+i] = akv[j][i]*sc;
        __syncwarp();
    }
}

// ---------------- CSR build: hist -> scan -> bucket --------------------------
__global__ __launch_bounds__(256) void k_hist(const int* __restrict__ recv){
    int e = blockIdx.x*256+threadIdx.x;
    if(e<Ne) atomicAdd(&g_cw[recv[e]],1);
}
__global__ __launch_bounds__(1024) void k_scan(){
    __shared__ int part[1024];
    int tid = threadIdx.x;
    int st = tid*10;
    int loc[10]; int s=0;
    #pragma unroll
    for(int i=0;i<10;i++){
        int v = (st+i<Nn)? g_cw[st+i] : 0;
        loc[i]=s; s+=v;
    }
    part[tid]=s; __syncthreads();
    for(int d=1; d<1024; d<<=1){
        int v = (tid>=d)? part[tid-d] : 0;
        __syncthreads();
        part[tid]+=v;
        __syncthreads();
    }
    int base = (tid==0)? 0 : part[tid-1];
    #pragma unroll
    for(int i=0;i<10;i++) if(st+i<Nn) g_off[st+i]=base+loc[i];
    if(tid==1023) g_off[Nn]=part[1023];
}
__global__ __launch_bounds__(256) void k_bucket(
    const int* __restrict__ recv, const int* __restrict__ send,
    const float* __restrict__ vecs)
{
    int e = blockIdx.x*256+threadIdx.x;
    if(e<Ne){
        int r = recv[e];
        int p = atomicAdd(&g_cw[Nn+r],1);
        int slot = g_off[r]+p;
        g_list[slot] = e;
        g_snd[slot]  = send[e];
        float vx=vecs[3*e], vy=vecs[3*e+1], vz=vecs[3*e+2];
        float invr = rsqrtf(vx*vx+vy*vy+vz*vz);
        g_uvec4[slot] = make_float4(vx*invr, vy*invr, vz*invr, 0.f);
    }
}

// ---------------- K2: radial MLP (W3 in fp16 smem -> 2 CTAs/SM) -------------
// smem floats: W1 512 | W2 4096 | W3h 10240 (half2=40KB) | radT 512
//            | H1T 4352 | H2T 4352  = 24064 floats = 96256 B
#define MLP_SMEM_FLOATS (512+4096+10240+512+4352+4352)
__global__ __launch_bounds__(256) void k_mlp(
    const float* __restrict__ vecs,
    const float* __restrict__ W1, const float* __restrict__ W2,
    const float* __restrict__ W3)
{
    extern __shared__ float sm[];
    float*   sW1  = sm;
    float*   sW2  = sm+512;
    __half2* sW3h = reinterpret_cast<__half2*>(sm+4608);   // 10240 half2
    float*   sRadT= sm+14848;    // [k][64]
    float*   sH1T = sm+15360;    // [k][68]
    float*   sH2T = sm+19712;    // [k][68]
    int tid = threadIdx.x;
    for(int i=tid;i<512;i+=256)   sW1[i]=W1[i];
    for(int i=tid;i<4096;i+=256)  sW2[i]=W2[i];
    for(int i=tid;i<10240;i+=256){
        const float2 w = *reinterpret_cast<const float2*>(&W3[2*i]);
        sW3h[i] = __floats2half2_rn(w.x, w.y);
    }
    __syncthreads();

    const float PI = 3.14159265358979f;
    const float SQRT2 = 1.41421356237f;

    int e1  = tid&63,  og1 = tid>>6;
    int ebl = (tid&15)*4, obl = (tid>>4)*4;
    int eg  = tid>>5,  ot  = tid&31;

    for(int tile=blockIdx.x; tile<Ne/64; tile+=gridDim.x){
        int ebase = tile*64;
        if(tid < 64){
            int e = ebase + tid;
            float x = vecs[3*e], y = vecs[3*e+1], z = vecs[3*e+2];
            float r = sqrtf(x*x+y*y+z*z);
            float r2 = r*r, r3 = r2*r;
            float x6 = r3*r3;
            float env = 1.f - 28.f*x6 + 48.f*x6*r - 21.f*x6*r2;
            if(r >= 1.f) env = 0.f;
            float coef = SQRT2*env/r;
            float pr = PI*r;
            #pragma unroll
            for(int k=0;k<8;k++) sRadT[k*64+tid] = coef*sinf((float)(k+1)*pr);
        }
        __syncthreads();
        {
            u64t a[8];
            #pragma unroll
            for(int j=0;j<8;j++) a[j]=0ULL;
            #pragma unroll
            for(int k=0;k<8;k++){
                float r = sRadT[k*64+e1];
                u64t rp = pk(r,r);
                #pragma unroll
                for(int j=0;j<8;j++){
                    u64t w = *(const u64t*)&sW1[k*64 + og1*16 + 2*j];
                    fma2(a[j], rp, w);
                }
            }
            #pragma unroll
            for(int j=0;j<8;j++){
                float2 v = up2(a[j]);
                sH1T[(og1*16+2*j)*68 + e1]   = sw(v.x*0.35355339059f);
                sH1T[(og1*16+2*j+1)*68 + e1] = sw(v.y*0.35355339059f);
            }
        }
        __syncthreads();
        {
            u64t b[4][2];
            #pragma unroll
            for(int i=0;i<4;i++){ b[i][0]=0ULL; b[i][1]=0ULL; }
            for(int k=0;k<64;k++){
                const float4 h = *(const float4*)&sH1T[k*68 + ebl];
                const ulonglong2 w = *(const ulonglong2*)&sW2[k*64 + obl];
                u64t h0=pk(h.x,h.x), h1=pk(h.y,h.y), h2v=pk(h.z,h.z), h3=pk(h.w,h.w);
                fma2(b[0][0],h0,w.x); fma2(b[0][1],h0,w.y);
                fma2(b[1][0],h1,w.x); fma2(b[1][1],h1,w.y);
                fma2(b[2][0],h2v,w.x); fma2(b[2][1],h2v,w.y);
                fma2(b[3][0],h3,w.x); fma2(b[3][1],h3,w.y);
            }
            #pragma unroll
            for(int i=0;i<4;i++){
                #pragma unroll
                for(int p=0;p<2;p++){
                    float2 v = up2(b[i][p]);
                    sH2T[(obl+2*p)*68 + ebl+i]   = sw(v.x*0.125f);
                    sH2T[(obl+2*p+1)*68 + ebl+i] = sw(v.y*0.125f);
                }
            }
        }
        __syncthreads();
        {
            u64t m[8][5];
            #pragma unroll
            for(int i=0;i<8;i++)
                #pragma unroll
                for(int j=0;j<5;j++) m[i][j]=0ULL;
            for(int k=0;k<64;k++){
                const float4 ha = *(const float4*)&sH2T[k*68 + eg*8];
                const float4 hb = *(const float4*)&sH2T[k*68 + eg*8 + 4];
                u64t wj[5];
                #pragma unroll
                for(int j=0;j<5;j++){
                    float2 wf = __half22float2(sW3h[k*160 + ot + 32*j]);
                    wj[j] = pk(wf.x, wf.y);
                }
                u64t hp;
                hp=pk(ha.x,ha.x);
                #pragma unroll
                for(int j=0;j<5;j++) fma2(m[0][j],hp,wj[j]);
                hp=pk(ha.y,ha.y);
                #pragma unroll
                for(int j=0;j<5;j++) fma2(m[1][j],hp,wj[j]);
                hp=pk(ha.z,ha.z);
                #pragma unroll
                for(int j=0;j<5;j++) fma2(m[2][j],hp,wj[j]);
                hp=pk(ha.w,ha.w);
                #pragma unroll
                for(int j=0;j<5;j++) fma2(m[3][j],hp,wj[j]);
                hp=pk(hb.x,hb.x);
                #pragma unroll
                for(int j=0;j<5;j++) fma2(m[4][j],hp,wj[j]);
                hp=pk(hb.y,hb.y);
                #pragma unroll
                for(int j=0;j<5;j++) fma2(m[5][j],hp,wj[j]);
                hp=pk(hb.z,hb.z);
                #pragma unroll
                for(int j=0;j<5;j++) fma2(m[6][j],hp,wj[j]);
                hp=pk(hb.w,hb.w);
                #pragma unroll
                for(int j=0;j<5;j++) fma2(m[7][j],hp,wj[j]);
            }
            const float S = 0.03125f;  // (1/8)*(1/4)
            #pragma unroll
            for(int i=0;i<8;i++){
                int e = ebase + eg*8 + i;
                float2 v0=up2(m[i][0]), v1=up2(m[i][1]), v2=up2(m[i][2]);
                float2 v3=up2(m[i][3]), v4=up2(m[i][4]);
                __half2 a01 = __floats2half2_rn(v0.x*S, v1.x*S);
                __half2 a23 = __floats2half2_rn(v2.x*S, v3.x*S);
                __half2 b01 = __floats2half2_rn(v0.y*S, v1.y*S);
                __half2 b23 = __floats2half2_rn(v2.y*S, v3.y*S);
                uint4 stv;
                stv.x = *(unsigned int*)&a01;
                stv.y = *(unsigned int*)&a23;
                stv.z = *(unsigned int*)&b01;
                stv.w = *(unsigned int*)&b23;
                *reinterpret_cast<uint4*>(&g_mixh[(size_t)e*128 + 4*ot]) = stv;
                __half2 wv = __floats2half2_rn(v4.x*S, v4.y*S);
                *reinterpret_cast<__half2*>(&g_mixwh[(size_t)e*64 + 2*ot]) = wv;
            }
        }
        __syncthreads();
    }
}

// ---------------- K3: CSR gather-aggregate (fp16 mix stream) ----------------
__global__ __launch_bounds__(256) void k_agg()
{
    __shared__ int slist[8][64];
    __shared__ int ssnd [8][64];
    int warp = threadIdx.x>>5, lane = threadIdx.x&31;
    const float SQRT3 = 1.73205080757f;
    const float CRS   = 1.22474487139f;  // sqrt(3)/sqrt(2)
    int n = blockIdx.x*8 + warp;
    if(n >= Nn) return;
    int k0 = g_off[n], k1 = g_off[n+1];
    float as[2]={0,0}, ats[2]={0,0};
    float amv[2][3]={{0,0,0},{0,0,0}};
    float asc[2][3]={{0,0,0},{0,0,0}};
    float acr[2][3]={{0,0,0},{0,0,0}};
    int* lst = slist[warp];
    int* snd = ssnd[warp];
    for(int base=k0; base<k1; base+=64){
        int chunk = min(64, k1-base);
        for(int i=lane;i<chunk;i+=32){
            lst[i] = g_list[base+i];
            snd[i] = g_snd[base+i];
        }
        __syncwarp();
        #pragma unroll 4
        for(int i=0;i<chunk;i++){
            int slot = base+i;
            int e = lst[i];
            int s = snd[i];
            float4 u4 = g_uvec4[slot];
            float ux=u4.x, uy=u4.y, uz=u4.z;
            const float4*  vu = g_v_up4 + (size_t)s*64;
            const __half2* mh = g_mixh + (size_t)e*128;
            const __half*  mw = g_mixwh + (size_t)e*64;
            #pragma unroll
            for(int t=0;t<2;t++){
                int c = lane + 32*t;
                float4 vv = vu[c];            // (vx,vy,vz, s_up)
                uint2 raw = __ldcs(reinterpret_cast<const uint2*>(mh + (size_t)c*2));
                __half2 h01 = *(__half2*)&raw.x;
                __half2 h23 = *(__half2*)&raw.y;
                float2 f01 = __half22float2(h01);
                float2 f23 = __half22float2(h23);
                float x0=f01.x, x1=f01.y, x2=f23.x, x3=f23.y;
                float x4 = __half2float(mw[c]);
                float  ms = vv.w;
                as[t]  += ms*x0;
                ats[t] += (vv.x*ux+vv.y*uy+vv.z*uz)*x1;
                amv[t][0] += vv.x*x2; amv[t][1] += vv.y*x2; amv[t][2] += vv.z*x2;
                float s3 = ms*SQRT3*x3;
                asc[t][0] += s3*ux; asc[t][1] += s3*uy; asc[t][2] += s3*uz;
                float c4 = CRS*x4;
                acr[t][0] += (vv.y*uz-vv.z*uy)*c4;
                acr[t][1] += (vv.z*ux-vv.x*uz)*c4;
                acr[t][2] += (vv.x*uy-vv.y*ux)*c4;
            }
        }
        __syncwarp();
    }
    #pragma unroll
    for(int t=0;t<2;t++){
        int c = lane + 32*t;
        g_agg_s[n*128+c]     = as[t];
        g_agg_s[n*128+64+c]  = ats[t];
        #pragma unroll
        for(int i3=0;i3<3;i3++){
            g_agg_v[(size_t)n*576 + i3*192 + c]       = amv[t][i3];
            g_agg_v[(size_t)n*576 + i3*192 + 64 + c]  = asc[t][i3];
            g_agg_v[(size_t)n*576 + i3*192 + 128 + c] = acr[t][i3];
        }
    }
}

// ---------------- K4: down-projection + skip + gate -> output (R5 version) --
// smem floats: Wds 16384 | Wdv 12288 | stage 8*704
#define OUT_SMEM_FLOATS (16384+12288+5632)
__global__ __launch_bounds__(256) void k_node_out(
    const float* __restrict__ Wds, const float* __restrict__ Wdv,
    float* __restrict__ out)
{
    extern __shared__ float sm[];
    float* sWds = sm;
    float* sWdv = sm+16384;
    float* sAgg = sm+16384+12288;
    int tid = threadIdx.x;
    for(int i=tid;i<16384;i+=256) sWds[i]=Wds[i];
    for(int i=tid;i<12288;i+=256) sWdv[i]=Wdv[i];
    __syncthreads();
    int warp = tid>>5, lane = tid&31;
    int gw = blockIdx.x*8+warp, nw = gridDim.x*8;
    const float ISNS = 0.08838834765f;  // 1/sqrt(128)
    const float ISNV = 0.07216878365f;  // 1/sqrt(192)
    float* st = sAgg + warp*704;
    for(int n=gw; n<Nn; n+=nw){
        for(int i=lane;i<128;i+=32) st[i]     = g_agg_s[n*128+i];
        for(int i=lane;i<576;i+=32) st[128+i] = g_agg_v[(size_t)n*576+i];
        __syncwarp();
        float os[4]={0,0,0,0};
        for(int c=0;c<128;c++){
            float a = st[c];
            #pragma unroll
            for(int j=0;j<4;j++) os[j] += a*sWds[c*128+lane+32*j];
        }
        float ov[2][3]={{0,0,0},{0,0,0}};
        for(int c=0;c<192;c++){
            float a0 = st[128+c], a1 = st[128+192+c], a2 = st[128+384+c];
            #pragma unroll
            for(int j=0;j<2;j++){
                float w = sWdv[c*64+lane+32*j];
                ov[j][0]+=a0*w; ov[j][1]+=a1*w; ov[j][2]+=a2*w;
            }
        }
        #pragma unroll
        for(int j=0;j<4;j++) os[j] = os[j]*ISNS + g_skip_s[n*128+lane+32*j];
        #pragma unroll
        for(int j=0;j<2;j++)
            #pragma unroll
            for(int i=0;i<3;i++)
                ov[j][i] = ov[j][i]*ISNV + g_skip_v[(size_t)n*192+3*(lane+32*j)+i];
        float g0 = sw(os[2]), g1 = sw(os[3]);
        float* o = out + (size_t)n*256;
        o[lane]    = sw(os[0]);
        o[lane+32] = sw(os[1]);
        #pragma unroll
        for(int i=0;i<3;i++){
            o[64+3*lane+i]      = ov[0][i]*g0;
            o[64+3*(lane+32)+i] = ov[1][i]*g1;
        }
        __syncwarp();
    }
}

// ---------------- launch ----------------------------------------------------
extern "C" void kernel_launch(void* const* d_in, const int* in_sizes, int n_in,
                              void* d_out, int out_size)
{
    const float* vectors  = (const float*)d_in[0];
    const float* node_s   = (const float*)d_in[1];
    const float* node_v   = (const float*)d_in[2];
    const int*   spec     = (const int*)  d_in[3];
    const int*   senders  = (const int*)  d_in[4];
    const int*   receivers= (const int*)  d_in[5];
    const float* Wss      = (const float*)d_in[6];
    const float* Wsv      = (const float*)d_in[7];
    const float* Wus      = (const float*)d_in[8];
    const float* Wuv      = (const float*)d_in[9];
    const float* W1       = (const float*)d_in[10];
    const float* W2       = (const float*)d_in[11];
    const float* W3       = (const float*)d_in[12];
    const float* Wds      = (const float*)d_in[13];
    const float* Wdv      = (const float*)d_in[14];
    float* out = (float*)d_out;

    void *pcw;
    cudaGetSymbolAddress(&pcw, g_cw);

    cudaFuncSetAttribute(k_mlp, cudaFuncAttributeMaxDynamicSharedMemorySize,
                         MLP_SMEM_FLOATS*4);
    cudaFuncSetAttribute(k_node_out, cudaFuncAttributeMaxDynamicSharedMemorySize,
                         OUT_SMEM_FLOATS*4);

    // fork-join: side stream builds CSR + node_prep concurrent with k_mlp
    cudaStream_t s2;
    cudaStreamCreateWithFlags(&s2, cudaStreamNonBlocking);
    cudaEvent_t evF, evJ;
    cudaEventCreateWithFlags(&evF, cudaEventDisableTiming);
    cudaEventCreateWithFlags(&evJ, cudaEventDisableTiming);

    cudaEventRecord(evF, 0);
    cudaStreamWaitEvent(s2, evF, 0);

    cudaMemsetAsync(pcw, 0, 2*Nn*sizeof(int), s2);
    k_hist  <<<(Ne+255)/256, 256, 0, s2>>>(receivers);
    k_scan  <<<1, 1024, 0, s2>>>();
    k_bucket<<<(Ne+255)/256, 256, 0, s2>>>(receivers, senders, vectors);
    k_node_prep<<<1250, 256, 0, s2>>>(node_s, node_v, spec, Wss, Wsv, Wus, Wuv);
    cudaEventRecord(evJ, s2);

    k_mlp<<<296, 256, MLP_SMEM_FLOATS*4>>>(vectors, W1, W2, W3);

    cudaStreamWaitEvent(0, evJ, 0);
    k_agg<<<1250, 256>>>();
    k_node_out<<<148, 256, OUT_SMEM_FLOATS*4>>>(Wds, Wdv, out);

    cudaEventDestroy(evF);
    cudaEventDestroy(evJ);
    cudaStreamDestroy(s2);
}